// round 7
// baseline (speedup 1.0000x reference)
#include <cuda_runtime.h>
#include <cstdint>
#include <cstddef>

#define NS   730
#define NG   1000
#define MUc  8
#define NCH  (NG*MUc)
#define BATCH 8
#define PRECSf 1e-05f
#define XS   (NG*3)          // 3000 floats per timestep in x
#define PS   (NG*13*MUc)     // 104000 floats per timestep in parameters

__constant__ float LBc[13] = {1.0f, 50.0f, 0.05f, 0.01f, 0.001f, 0.2f, 0.0f, 0.0f, -2.5f, 0.5f, 0.0f, 0.0f, 0.3f};
__constant__ float UBc[13] = {6.0f, 1000.0f, 0.9f, 0.5f, 0.2f, 1.0f, 10.0f, 100.0f, 2.5f, 10.0f, 0.1f, 0.2f, 5.0f};

__device__ __forceinline__ float fast_lg2(float a) {
    float r; asm("lg2.approx.f32 %0, %1;" : "=f"(r) : "f"(a)); return r;
}
__device__ __forceinline__ float fast_ex2(float a) {
    float r; asm("ex2.approx.f32 %0, %1;" : "=f"(r) : "f"(a)); return r;
}

// ============================================================================
// Specialized path: time-varying slots are exactly {12=BETAET, 0=BETA}.
// ============================================================================
__device__ __forceinline__ void run_spec(
    const float* __restrict__ x, const float* __restrict__ par,
    float* __restrict__ out, int g, int m, int staind,
    const float* __restrict__ ppBET, const float* __restrict__ ppB)
{
    // ---- chain-constant parameters from the staind row ----
    float cp[13];
    {
        const float* pb = par + ((size_t)staind*NG + (size_t)g)*13u*MUc + m;
        #pragma unroll
        for (int p = 0; p < 13; p++)
            cp[p] = fmaf(pb[p*MUc], (UBc[p]-LBc[p]), LBc[p]);
    }
    const float FC=cp[1], K0=cp[2], K1=cp[3], K2=cp[4], LP=cp[5],
                PERCc=cp[6], UZL=cp[7], TT=cp[8], CFMAX=cp[9], CFR=cp[10], CWH=cp[11];
    const float lgFC       = fast_lg2(FC);
    const float neglgLPFC  = -fast_lg2(LP*FC);
    const float negCFMAXTT = -CFMAX*TT;     // m0 = CFMAX*T + negCFMAXTT
    const float negCFR     = -CFR;
    const float negCWH     = -CWH;
    const float dBET = UBc[12]-LBc[12], lbBET = LBc[12];
    const float dB   = UBc[0] -LBc[0],  lbB   = LBc[0];

    float SP=0.001f, MW=0.001f, SM=0.001f, SUZ=0.001f, SLZ=0.001f;
    const float invmu = 1.0f/(float)MUc;
    const unsigned FULL = 0xffffffffu;
    const bool hi4 = (m & 4) != 0, hi2 = (m & 2) != 0, hi1 = (m & 1) != 0;

    // one step with fused precompute; updates state, returns Q
    auto step = [&](float P_, float T_, float E_, float BTraw, float Braw) -> float {
        float BETAET = fmaf(BTraw, dBET, lbBET);
        float BETA   = fmaf(Braw,  dB,   lbB);
        float m0 = fmaf(CFMAX, T_, negCFMAXTT);      // CFMAX*(T-TT)
        float mm = fmaxf(m0, 0.0f);
        float rr = fmaxf(negCFR*m0, 0.0f);           // max(CFR*CFMAX*(TT-T),0)
        bool  wet = (T_ >= TT);
        float rain = wet ? P_ : 0.0f;
        float snow = wet ? 0.0f : P_;
        float C1 = -BETA*lgFC;
        float C2 = fmaf(BETAET, neglgLPFC, fast_lg2(E_));
        // snow module
        SP += snow;
        float melt = fminf(mm, SP);
        MW += melt; SP -= melt;
        float refr = fminf(rr, MW);
        SP += refr; MW -= refr;
        float tosoil = fmaxf(fmaf(negCWH, SP, MW), 0.0f);
        MW -= tosoil;
        float rt = rain + tosoil;
        // soil module — loop-carried critical chain
        float lgSM = fast_lg2(SM);
        float sw   = fast_ex2(fminf(fmaf(BETA, lgSM, C1), 0.0f));
        float recharge = rt * sw;
        float smrt = SM + rt;
        float SM1  = smrt - recharge;
        float SM2  = fminf(SM1, FC);
        float excess = SM1 - SM2;
        float lgSM2 = fast_lg2(SM2);
        float ea    = fast_ex2(fmaf(BETAET, lgSM2, C2));  // E*(SM2/(LP*FC))^BETAET
        float ETact = fminf(fminf(SM2, E_), ea);
        SM = fmaxf(SM2 - ETact, PRECSf);
        // routing
        SUZ += recharge + excess;
        float PERC = fminf(SUZ, PERCc);
        SUZ -= PERC;
        float Q0 = K0 * fmaxf(SUZ - UZL, 0.0f);
        SUZ -= Q0;
        float Q1 = K1 * SUZ;
        SUZ -= Q1;
        SLZ += PERC;
        float Q2 = K2 * SLZ;
        SLZ -= Q2;
        return Q0 + Q1 + Q2;
    };

    auto do_batch = [&](const float* P, const float* T, const float* E,
                        const float* BT, const float* BR, float* dst) {
        float q[BATCH];
        #pragma unroll
        for (int j = 0; j < BATCH; j++)
            q[j] = step(P[j], T[j], E[j], BT[j], BR[j]);
        // recursive-halving reduce-scatter: lane m owns total of step base+m
        float s1[4];
        #pragma unroll
        for (int e = 0; e < 4; e++) {
            float send = hi4 ? q[e] : q[e+4];
            float recv = __shfl_xor_sync(FULL, send, 4);
            s1[e] = (hi4 ? q[e+4] : q[e]) + recv;
        }
        float s2[2];
        #pragma unroll
        for (int e = 0; e < 2; e++) {
            float send = hi2 ? s1[e] : s1[e+2];
            float recv = __shfl_xor_sync(FULL, send, 2);
            s2[e] = (hi2 ? s1[e+2] : s1[e]) + recv;
        }
        float send = hi1 ? s2[0] : s2[1];
        float recv = __shfl_xor_sync(FULL, send, 1);
        float tot  = (hi1 ? s2[1] : s2[0]) + recv;
        *dst = tot * invmu;
    };

    // ---- strength-reduced streaming pointers (A = even batches, B = odd) ----
    const float* xA  = x + g*3;          const float* xB  = xA  + BATCH*XS;
    const float* tA  = ppBET;            const float* tB  = tA  + BATCH*PS;
    const float* bA  = ppB;              const float* bB  = bA  + BATCH*PS;
    float*       outp = out + (size_t)m*NG + g;

    float aP[BATCH], aT[BATCH], aE[BATCH], aBT[BATCH], aB[BATCH];
    float bP[BATCH], bT[BATCH], bE[BATCH], bBT[BATCH], bB_[BATCH];

    // prologue: load batch 0 into A
    #pragma unroll
    for (int j = 0; j < BATCH; j++) {
        aP [j] = xA[j*XS + 0];
        aT [j] = xA[j*XS + 1];
        aE [j] = xA[j*XS + 2];
        aBT[j] = tA[j*PS];
        aB [j] = bA[j*PS];
    }

    // 45 unrolled iterations cover batches 0..89; A ends holding batch 90.
    for (int it = 0; it < 45; it++) {
        // prefetch B = batch 2it+1 (<= 89, in-bounds)
        #pragma unroll
        for (int j = 0; j < BATCH; j++) {
            bP [j] = xB[j*XS + 0];
            bT [j] = xB[j*XS + 1];
            bE [j] = xB[j*XS + 2];
            bBT[j] = tB[j*PS];
            bB_[j] = bB[j*PS];
        }
        // compute A = batch 2it
        do_batch(aP, aT, aE, aBT, aB, outp);
        // advance A pointers to batch 2it+2 (<= 90, in-bounds) and prefetch
        xA += 2*BATCH*XS;  tA += 2*BATCH*PS;  bA += 2*BATCH*PS;
        #pragma unroll
        for (int j = 0; j < BATCH; j++) {
            aP [j] = xA[j*XS + 0];
            aT [j] = xA[j*XS + 1];
            aE [j] = xA[j*XS + 2];
            aBT[j] = tA[j*PS];
            aB [j] = bA[j*PS];
        }
        // compute B = batch 2it+1
        do_batch(bP, bT, bE, bBT, bB_, outp + BATCH*NG);
        xB += 2*BATCH*XS;  tB += 2*BATCH*PS;  bB += 2*BATCH*PS;
        outp += 2*BATCH*NG;
    }
    // final full batch 90 (steps 720..727)
    do_batch(aP, aT, aE, aBT, aB, outp);

    // tail: steps 728, 729
    const float* xt = x + g*3;
    #pragma unroll
    for (int t = 91*BATCH; t < NS; t++) {
        float qv = step(xt[(long)t*XS + 0], xt[(long)t*XS + 1], xt[(long)t*XS + 2],
                        ppBET[(long)t*PS], ppB[(long)t*PS]);
        qv += __shfl_xor_sync(FULL, qv, 1);
        qv += __shfl_xor_sync(FULL, qv, 2);
        qv += __shfl_xor_sync(FULL, qv, 4);
        if (m == 0) out[(size_t)t*NG + g] = qv * invmu;
    }
}

// ============================================================================
// Generic fallback (any i0/i1).
// ============================================================================
__device__ __forceinline__ void run_generic(
    const float* __restrict__ x, const float* __restrict__ par,
    float* __restrict__ out, int g, int m, int staind, int i0, int i1)
{
    float cp[13];
    {
        const float* pb = par + ((size_t)staind*NG + (size_t)g)*13u*MUc + m;
        #pragma unroll
        for (int p = 0; p < 13; p++)
            cp[p] = fmaf(pb[p*MUc], (UBc[p]-LBc[p]), LBc[p]);
    }
    const float lb0 = LBc[i0], d0 = UBc[i0]-LBc[i0];
    const float lb1 = LBc[i1], d1 = UBc[i1]-LBc[i1];
    const float* xp  = x   + (size_t)g*3;
    const float* pp0 = par + ((size_t)g*13 + (size_t)i0)*MUc + m;
    const float* pp1 = par + ((size_t)g*13 + (size_t)i1)*MUc + m;

    float SP=0.001f, MW=0.001f, SM=0.001f, SUZ=0.001f, SLZ=0.001f;
    const float invmu = 1.0f/(float)MUc;
    const unsigned FULL = 0xffffffffu;

    for (int t = 0; t < NS; t++) {
        float P_ = xp[(long)t*XS + 0];
        float T_ = xp[(long)t*XS + 1];
        float E_ = xp[(long)t*XS + 2];
        float v0 = fmaf(pp0[(long)t*PS], d0, lb0);
        float v1 = fmaf(pp1[(long)t*PS], d1, lb1);
        float pr[13];
        #pragma unroll
        for (int p = 0; p < 13; p++) {
            float v = cp[p];
            if (p == i0) v = v0;
            if (p == i1) v = v1;
            pr[p] = v;
        }
        float BETA=pr[0], FC=pr[1], K0=pr[2], K1=pr[3], K2=pr[4], LP=pr[5],
              PERCc=pr[6], UZL=pr[7], TT=pr[8], CFMAX=pr[9], CFR=pr[10],
              CWH=pr[11], BETAET=pr[12];
        float rain = (T_ >= TT) ? P_ : 0.0f;
        float snow = P_ - rain;
        SP += snow;
        float melt = fminf(fmaxf(CFMAX*(T_-TT), 0.0f), SP);
        MW += melt; SP -= melt;
        float refr = fminf(fmaxf(CFR*CFMAX*(TT-T_), 0.0f), MW);
        SP += refr; MW -= refr;
        float tosoil = fmaxf(MW - CWH*SP, 0.0f);
        MW -= tosoil;
        float sw = fminf(fast_ex2(BETA*(fast_lg2(SM) - fast_lg2(FC))), 1.0f);
        float rt = rain + tosoil;
        float recharge = rt * sw;
        float SM1 = SM + rt - recharge;
        float excess = fmaxf(SM1 - FC, 0.0f);
        float SM2 = SM1 - excess;
        float ef = fminf(fast_ex2(BETAET*(fast_lg2(SM2) - fast_lg2(LP*FC))), 1.0f);
        float ETact = fminf(SM2, E_*ef);
        SM = fmaxf(SM2 - ETact, PRECSf);
        SUZ += recharge + excess;
        float PERC = fminf(SUZ, PERCc);
        SUZ -= PERC;
        float Q0 = K0 * fmaxf(SUZ - UZL, 0.0f);
        SUZ -= Q0;
        float Q1 = K1 * SUZ;
        SUZ -= Q1;
        SLZ += PERC;
        float Q2 = K2 * SLZ;
        SLZ -= Q2;
        float qv = Q0 + Q1 + Q2;
        qv += __shfl_xor_sync(FULL, qv, 1);
        qv += __shfl_xor_sync(FULL, qv, 2);
        qv += __shfl_xor_sync(FULL, qv, 4);
        if (m == 0) out[(size_t)t*NG + g] = qv * invmu;
    }
}

__global__ void __launch_bounds__(64, 1)
hbv_kernel(const float* __restrict__ x, const float* __restrict__ par,
           const int* __restrict__ staind_p, const int* __restrict__ tdlst_p,
           int n_td, float* __restrict__ out)
{
    int tid = blockIdx.x * 64 + threadIdx.x;   // 8000 threads exactly
    int g = tid >> 3;
    int m = tid & 7;
    int staind = staind_p[0];
    int t0 = tdlst_p[0];
    int t1 = (n_td > 1) ? tdlst_p[1] : t0;
    int i0 = ((t0 - 1) % 13 + 13) % 13;
    int i1 = ((t1 - 1) % 13 + 13) % 13;

    const long PS_base = (size_t)g*13*MUc + m;
    if ((i0 == 12 && i1 == 0) || (i0 == 0 && i1 == 12)) {
        run_spec(x, par, out, g, m, staind,
                 par + PS_base + 12*MUc, par + PS_base + 0*MUc);
    } else {
        run_generic(x, par, out, g, m, staind, i0, i1);
    }
}

extern "C" void kernel_launch(void* const* d_in, const int* in_sizes, int n_in,
                              void* d_out, int out_size)
{
    const float* x      = (const float*)d_in[0];   // (730, 1000, 3) f32
    const float* par    = (const float*)d_in[1];   // (730, 1000, 13, 8) f32
    const int*   staind = (const int*)d_in[2];     // scalar
    const int*   tdlst  = (const int*)d_in[3];     // (2,) int32
    int n_td = in_sizes[3];
    (void)n_in; (void)out_size;
    hbv_kernel<<<NCH/64, 64>>>(x, par, staind, tdlst, n_td, (float*)d_out);
}